// round 10
// baseline (speedup 1.0000x reference)
#include <cuda_runtime.h>
#include <cuda_bf16.h>
#include <cuda_fp16.h>
#include <cstdint>

#define N_NODES 10000
#define M_PAD   10112     // 79 tiles of 128
#define N_EDGES 160000
#define F0      50
#define HID     512
#define F2      121
#define N2      256
#define KA1     256
#define KB1     384
#define KA2     1024
#define KB2     1536

// ---------------- scratch (device globals; zero-initialized) -----------------
__device__ int   g_is64;
__device__ __align__(16) int   g_deg[N_NODES + 16];
__device__ __align__(16) int   g_rowstart[N_NODES + 16];
__device__ __align__(16) int   g_cursor[N_NODES + 16];
__device__ __align__(16) float g_invdeg[N_NODES + 16];
__device__ int   g_esrc[N_EDGES];
__device__ __align__(16) __nv_bfloat16 g_a1[(size_t)M_PAD * KA1];
__device__ __align__(16) __nv_bfloat16 g_b1p[(size_t)HID * KB1];
__device__ __align__(16) __nv_bfloat16 g_a2[(size_t)M_PAD * KA2];
__device__ __align__(16) __nv_bfloat16 g_b2p[(size_t)N2 * KB2];
__device__ __align__(16) __half g_qh[(size_t)M_PAD * 128];   // q (cols 0..120) fp16
__device__ __align__(16) float  g_r[(size_t)M_PAD * 128];    // r (cols 0..120) fp32

// ---------------- PTX helpers -------------------------------------------------
__device__ __forceinline__ uint32_t smem_u32(const void* p) {
    uint32_t a;
    asm("{ .reg .u64 t; cvta.to.shared.u64 t, %1; cvt.u32.u64 %0, t; }" : "=r"(a) : "l"(p));
    return a;
}
#define CP16(dst, src) \
    asm volatile("cp.async.cg.shared.global [%0], [%1], 16;" :: "r"(dst), "l"(src) : "memory")
#define CP_COMMIT() asm volatile("cp.async.commit_group;" ::: "memory")
#define CP_WAIT(n)  asm volatile("cp.async.wait_group %0;" :: "n"(n) : "memory")
#define LDSM_X4(r0, r1, r2, r3, addr) \
    asm volatile("ldmatrix.sync.aligned.m8n8.x4.shared.b16 {%0,%1,%2,%3}, [%4];" \
                 : "=r"(r0), "=r"(r1), "=r"(r2), "=r"(r3) : "r"(addr))
#define LDSM_X2(r0, r1, addr) \
    asm volatile("ldmatrix.sync.aligned.m8n8.x2.shared.b16 {%0,%1}, [%2];" \
                 : "=r"(r0), "=r"(r1) : "r"(addr))

__device__ __forceinline__ void mma16816(float* d, const uint32_t* a, const uint32_t* b) {
    asm volatile(
        "mma.sync.aligned.m16n8k16.row.col.f32.bf16.bf16.f32 "
        "{%0,%1,%2,%3}, {%4,%5,%6,%7}, {%8,%9}, {%0,%1,%2,%3};"
        : "+f"(d[0]), "+f"(d[1]), "+f"(d[2]), "+f"(d[3])
        : "r"(a[0]), "r"(a[1]), "r"(a[2]), "r"(a[3]), "r"(b[0]), "r"(b[1]));
}

// ---------------- hi/lo helpers ----------------------------------------------
__device__ __forceinline__ void hilo(float v, __nv_bfloat16& h, __nv_bfloat16& l) {
    h = __float2bfloat16_rn(v);
    l = __float2bfloat16_rn(v - __bfloat162float(h));
}

// ---------------- prep: zero deg + dtype detect + weight packs ---------------
__global__ void prep_kernel(const int* __restrict__ ei32,
                            const float* __restrict__ W1l, const float* __restrict__ W1r,
                            const float* __restrict__ W2l, const float* __restrict__ W2r) {
    int idx = blockIdx.x * blockDim.x + threadIdx.x;
    if (idx < N_NODES) g_deg[idx] = 0;
    if (blockIdx.x == 0 && threadIdx.x < 32) {
        int lane = threadIdx.x;
        int nz = 0;
#pragma unroll
        for (int r = 0; r < 4; r++) nz |= (ei32[1 + 2 * (lane + r * 32)] != 0);
        unsigned any = __ballot_sync(0xFFFFFFFFu, nz);
        if (lane == 0) g_is64 = any ? 0 : 1;
    }
    if (idx < HID * 112) {
        int k = idx % 112, n = idx / 112;
        float v = 0.f;
        if (k < F0)            v = W1l[k * HID + n];
        else if (k < 2 * F0)   v = W1r[(k - F0) * HID + n];
        __nv_bfloat16 h, l; hilo(v, h, l);
        size_t rb = (size_t)n * KB1;
        g_b1p[rb + k] = h; g_b1p[rb + 128 + k] = l; g_b1p[rb + 256 + k] = h;
    } else {
        int i2 = idx - HID * 112;
        if (i2 < N2 * HID) {
            int k = i2 % HID, n = i2 / HID;
            float v = 0.f;
            if (n < F2)            v = W2l[k * F2 + n];
            else if (n < 2 * F2)   v = W2r[k * F2 + (n - F2)];
            __nv_bfloat16 h, l; hilo(v, h, l);
            size_t rb = (size_t)n * KB2;
            g_b2p[rb + k] = h; g_b2p[rb + 512 + k] = l; g_b2p[rb + 1024 + k] = h;
        }
    }
}

__device__ __forceinline__ int load_idx(const void* ei, int pos) {
    int v = g_is64 ? (int)((const long long*)ei)[pos] : ((const int*)ei)[pos];
    return min(max(v, 0), N_NODES - 1);
}

// ---------------- CSR build --------------------------------------------------
__global__ void count_kernel(const void* __restrict__ ei) {
    int e = blockIdx.x * blockDim.x + threadIdx.x;
    if (e < N_EDGES) atomicAdd(&g_deg[load_idx(ei, N_EDGES + e)], 1);
}

// Vectorized two-level shfl scan: 640 threads x 16 elems (int4), 3 barriers.
__global__ void scan_kernel() {
    const int CH = 16;
    __shared__ int s_w[32];
    int t = threadIdx.x, lane = t & 31, wid = t >> 5;
    int base = t * CH;
    int local[CH];
    int sum = 0;
    if (base < N_NODES) {
#pragma unroll
        for (int v4 = 0; v4 < 4; v4++) {
            int4 v = *reinterpret_cast<const int4*>(&g_deg[base + v4 * 4]);
            local[v4 * 4 + 0] = v.x; local[v4 * 4 + 1] = v.y;
            local[v4 * 4 + 2] = v.z; local[v4 * 4 + 3] = v.w;
            sum += v.x + v.y + v.z + v.w;
        }
    } else {
#pragma unroll
        for (int i = 0; i < CH; i++) local[i] = 0;
    }
    if (t < 32) s_w[t] = 0;
    __syncthreads();
    int incl = sum;
#pragma unroll
    for (int off = 1; off < 32; off <<= 1) {
        int v = __shfl_up_sync(0xFFFFFFFFu, incl, off);
        if (lane >= off) incl += v;
    }
    if (lane == 31) s_w[wid] = incl;
    __syncthreads();
    if (wid == 0) {
        int v = s_w[lane];
        int wi = v;
#pragma unroll
        for (int off = 1; off < 32; off <<= 1) {
            int u = __shfl_up_sync(0xFFFFFFFFu, wi, off);
            if (lane >= off) wi += u;
        }
        s_w[lane] = wi - v;
    }
    __syncthreads();
    if (base >= N_NODES) return;
    int excl = s_w[wid] + (incl - sum);
#pragma unroll
    for (int v4 = 0; v4 < 4; v4++) {
        int4 rs; float4 iv;
        int d0 = local[v4 * 4 + 0], d1 = local[v4 * 4 + 1];
        int d2 = local[v4 * 4 + 2], d3 = local[v4 * 4 + 3];
        rs.x = excl;            rs.y = excl + d0;
        rs.z = excl + d0 + d1;  rs.w = excl + d0 + d1 + d2;
        excl += d0 + d1 + d2 + d3;
        iv.x = 1.0f / (float)(d0 > 1 ? d0 : 1);
        iv.y = 1.0f / (float)(d1 > 1 ? d1 : 1);
        iv.z = 1.0f / (float)(d2 > 1 ? d2 : 1);
        iv.w = 1.0f / (float)(d3 > 1 ? d3 : 1);
        *reinterpret_cast<int4*>(&g_rowstart[base + v4 * 4]) = rs;
        *reinterpret_cast<int4*>(&g_cursor[base + v4 * 4])   = rs;
        *reinterpret_cast<float4*>(&g_invdeg[base + v4 * 4]) = iv;
    }
}

__global__ void bucket_kernel(const void* __restrict__ ei) {
    int e = blockIdx.x * blockDim.x + threadIdx.x;
    if (e < N_EDGES) {
        int dst = load_idx(ei, N_EDGES + e);
        int pos = atomicAdd(&g_cursor[dst], 1);
        pos = min(max(pos, 0), N_EDGES - 1);
        g_esrc[pos] = load_idx(ei, e);
    }
}

// ---------------- layer-1 aggregation + A1 pack (2 panels: hi | lo) ----------
__global__ void aggx_pack_kernel(const float* __restrict__ x) {
    int gw = (blockIdx.x * blockDim.x + threadIdx.x) >> 5;
    int lane = threadIdx.x & 31;
    if (gw >= N_NODES) return;
    int beg = g_rowstart[gw], d = g_deg[gw];
    float s0 = 0.f, s1 = 0.f;
    int i = 0;
    for (; i + 4 <= d; i += 4) {
        int sa = g_esrc[beg + i],     sb = g_esrc[beg + i + 1];
        int sc = g_esrc[beg + i + 2], sd = g_esrc[beg + i + 3];
        const float* xa = x + sa * F0;
        const float* xb = x + sb * F0;
        const float* xc = x + sc * F0;
        const float* xd = x + sd * F0;
        s0 += xa[lane] + xb[lane] + xc[lane] + xd[lane];
        if (lane < F0 - 32)
            s1 += xa[lane + 32] + xb[lane + 32] + xc[lane + 32] + xd[lane + 32];
    }
    for (; i < d; i++) {
        const float* xa = x + g_esrc[beg + i] * F0;
        s0 += xa[lane];
        if (lane < F0 - 32) s1 += xa[lane + 32];
    }
    float inv = g_invdeg[gw];
    const float* xs = x + gw * F0;
    size_t rb = (size_t)gw * KA1;
    __nv_bfloat16 h, l;
#define WR_A1(j, v) do { hilo((v), h, l); g_a1[rb + (j)] = h; g_a1[rb + 128 + (j)] = l; } while (0)
    WR_A1(lane, s0 * inv);
    if (lane < F0 - 32) WR_A1(lane + 32, s1 * inv);
    WR_A1(F0 + lane, xs[lane]);
    if (lane < F0 - 32) WR_A1(F0 + lane + 32, xs[lane + 32]);
#undef WR_A1
}

// ---------------- mma.sync GEMM: C[128x128 tile] = A B^T ---------------------
#define BK      64
#define LDPAD   72        // bf16 elems per smem row (64 + 8 pad) = 144B
#define ROWB    (LDPAD * 2)
#define TILE_B  (128 * ROWB)        // 18432 bytes per operand per stage

template <int MODE>
__global__ void __launch_bounds__(256) mma_gemm_kernel(const float* __restrict__ bias) {
    constexpr int C  = (MODE == 1) ? 6 : 24;
    constexpr int KA = (MODE == 1) ? KA1 : KA2;
    constexpr int KB = (MODE == 1) ? KB1 : KB2;
    const __nv_bfloat16* Ag = (MODE == 1) ? g_a1 : g_a2;
    const __nv_bfloat16* Bg = (MODE == 1) ? g_b1p : g_b2p;

    extern __shared__ __align__(16) char dsm[];
    uint32_t sb = smem_u32(dsm);

    int tid = threadIdx.x, wid = tid >> 5, lane = tid & 31;
    int wm = wid & 1, wn = wid >> 1;       // warp grid 2 (M) x 4 (N)
    int mbase = blockIdx.y * 128, nbase = blockIdx.x * 128;

    float acc[4][4][4];
#pragma unroll
    for (int i = 0; i < 4; i++)
#pragma unroll
        for (int j = 0; j < 4; j++)
#pragma unroll
            for (int k = 0; k < 4; k++) acc[i][j][k] = 0.f;

    uint32_t a_off[4], b_off[4];
#pragma unroll
    for (int mi = 0; mi < 4; mi++)
        a_off[mi] = (uint32_t)(wm * 64 + mi * 16 + (lane & 15)) * ROWB + (uint32_t)(lane >> 4) * 16u;
#pragma unroll
    for (int ni = 0; ni < 4; ni++)
        b_off[ni] = (uint32_t)(wn * 32 + ni * 8 + (lane & 7)) * ROWB + (uint32_t)((lane >> 3) & 1) * 16u;

    auto aoff_of = [](int c) -> int {
        if (MODE == 1) {
            const int m[6] = {0, 64, 0, 64, 128, 192};
            return m[c];
        } else {
            return (c < 16) ? (c & 7) * 64 : 512 + (c - 16) * 64;
        }
    };

    auto load_chunk = [&](int c, int s) {
        uint32_t da = sb + s * 2 * TILE_B;
        uint32_t db = da + TILE_B;
        const __nv_bfloat16* asrc = Ag + (size_t)mbase * KA + aoff_of(c);
        const __nv_bfloat16* bsrc = Bg + (size_t)nbase * KB + c * BK;
#pragma unroll
        for (int i = 0; i < 4; i++) {
            int seg = tid + i * 256;
            int row = seg >> 3, s16 = seg & 7;
            uint32_t off = row * ROWB + s16 * 16;
            CP16(da + off, asrc + (size_t)row * KA + s16 * 8);
            CP16(db + off, bsrc + (size_t)row * KB + s16 * 8);
        }
        CP_COMMIT();
    };

    load_chunk(0, 0);

    for (int c = 0; c < C; ++c) {
        int s = c & 1;
        if (c + 1 < C) { load_chunk(c + 1, s ^ 1); CP_WAIT(1); }
        else           { CP_WAIT(0); }
        __syncthreads();

        uint32_t As = sb + s * 2 * TILE_B;
        uint32_t Bs = As + TILE_B;
#pragma unroll
        for (int k16 = 0; k16 < BK / 16; ++k16) {
            uint32_t afr[4][4], bfr[4][2];
#pragma unroll
            for (int mi = 0; mi < 4; mi++)
                LDSM_X4(afr[mi][0], afr[mi][1], afr[mi][2], afr[mi][3],
                        As + a_off[mi] + k16 * 32u);
#pragma unroll
            for (int ni = 0; ni < 4; ni++)
                LDSM_X2(bfr[ni][0], bfr[ni][1], Bs + b_off[ni] + k16 * 32u);
#pragma unroll
            for (int mi = 0; mi < 4; mi++)
#pragma unroll
                for (int ni = 0; ni < 4; ni++)
                    mma16816(acc[mi][ni], afr[mi], bfr[ni]);
        }
        __syncthreads();
    }

    // ---- epilogue ----
    int lr = lane >> 2, lc = lane & 3;
#pragma unroll
    for (int mi = 0; mi < 4; mi++) {
        int row0 = mbase + wm * 64 + mi * 16 + lr;
        int row1 = row0 + 8;
#pragma unroll
        for (int ni = 0; ni < 4; ni++) {
            int col0 = nbase + wn * 32 + ni * 8 + lc * 2;
            float* d = acc[mi][ni];
            if (MODE == 1) {
                float bb0 = bias[col0], bb1 = bias[col0 + 1];
#pragma unroll
                for (int hf = 0; hf < 2; hf++) {
                    int r = hf ? row1 : row0;
                    if (r >= N_NODES) continue;
                    float v0 = fmaxf(d[hf * 2 + 0] + bb0, 0.f);
                    float v1 = fmaxf(d[hf * 2 + 1] + bb1, 0.f);
                    __nv_bfloat16 h0, l0, h1, l1;
                    hilo(v0, h0, l0); hilo(v1, h1, l1);
                    size_t rb = (size_t)r * KA2;
                    __nv_bfloat162 hp; hp.x = h0; hp.y = h1;
                    __nv_bfloat162 lp; lp.x = l0; lp.y = l1;
                    *reinterpret_cast<__nv_bfloat162*>(&g_a2[rb + col0]) = hp;
                    *reinterpret_cast<__nv_bfloat162*>(&g_a2[rb + 512 + col0]) = lp;
                }
            } else {
#pragma unroll
                for (int hf = 0; hf < 2; hf++) {
                    int r = hf ? row1 : row0;
                    if (r >= N_NODES) continue;
#pragma unroll
                    for (int e = 0; e < 2; e++) {
                        int col = col0 + e;
                        float v = d[hf * 2 + e];
                        if (col < F2)
                            g_qh[(size_t)r * 128 + col] = __float2half_rn(v);
                        else if (col < 2 * F2)
                            g_r[(size_t)r * 128 + (col - F2)] = v;
                    }
                }
            }
        }
    }
}

// ---------------- final: out = mean_agg(q) + r + b2 --------------------------
__device__ __forceinline__ void acc_qh(uint2 u, float& a0, float& a1, float& a2, float& a3) {
    __half2 h01 = *reinterpret_cast<__half2*>(&u.x);
    __half2 h23 = *reinterpret_cast<__half2*>(&u.y);
    float2 f01 = __half22float2(h01), f23 = __half22float2(h23);
    a0 += f01.x; a1 += f01.y; a2 += f23.x; a3 += f23.y;
}

__global__ void final_kernel(const float* __restrict__ b2, float* __restrict__ out) {
    int gw = (blockIdx.x * blockDim.x + threadIdx.x) >> 5;
    int lane = threadIdx.x & 31;
    if (gw >= N_NODES) return;
    int beg = g_rowstart[gw], d = g_deg[gw];
    int j4 = lane * 4;                     // 0..124
    float a0 = 0.f, a1 = 0.f, a2 = 0.f, a3 = 0.f;
    int i = 0;
    for (; i + 4 <= d; i += 4) {
        int s0 = g_esrc[beg + i],     s1 = g_esrc[beg + i + 1];
        int s2 = g_esrc[beg + i + 2], s3 = g_esrc[beg + i + 3];
        uint2 u0 = *reinterpret_cast<const uint2*>(g_qh + (size_t)s0 * 128 + j4);
        uint2 u1 = *reinterpret_cast<const uint2*>(g_qh + (size_t)s1 * 128 + j4);
        uint2 u2 = *reinterpret_cast<const uint2*>(g_qh + (size_t)s2 * 128 + j4);
        uint2 u3 = *reinterpret_cast<const uint2*>(g_qh + (size_t)s3 * 128 + j4);
        acc_qh(u0, a0, a1, a2, a3);
        acc_qh(u1, a0, a1, a2, a3);
        acc_qh(u2, a0, a1, a2, a3);
        acc_qh(u3, a0, a1, a2, a3);
    }
    for (; i < d; i++) {
        int s0 = g_esrc[beg + i];
        uint2 u0 = *reinterpret_cast<const uint2*>(g_qh + (size_t)s0 * 128 + j4);
        acc_qh(u0, a0, a1, a2, a3);
    }
    float inv = g_invdeg[gw];
    float av[4] = {a0, a1, a2, a3};
    float* orow = out + (size_t)gw * F2;
    const float* rrow = g_r + (size_t)gw * 128;
#pragma unroll
    for (int c = 0; c < 4; c++) {
        int jj = j4 + c;
        if (jj < F2) orow[jj] = av[c] * inv + rrow[jj] + b2[jj];
    }
}

// ---------------- launch ------------------------------------------------------
extern "C" void kernel_launch(void* const* d_in, const int* in_sizes, int n_in,
                              void* d_out, int out_size) {
    const float* x   = (const float*)d_in[0];
    const void*  ei  = d_in[1];
    const float* W1l = (const float*)d_in[2];
    const float* W1r = (const float*)d_in[3];
    const float* b1  = (const float*)d_in[4];
    const float* W2l = (const float*)d_in[5];
    const float* W2r = (const float*)d_in[6];
    const float* b2  = (const float*)d_in[7];
    float*       out = (float*)d_out;

    const int SMEM_DYN = 4 * TILE_B;   // 73728 bytes: 2 stages x (A + B)
    static bool attr_set = false;
    if (!attr_set) {
        cudaFuncSetAttribute(mma_gemm_kernel<1>, cudaFuncAttributeMaxDynamicSharedMemorySize, SMEM_DYN);
        cudaFuncSetAttribute(mma_gemm_kernel<2>, cudaFuncAttributeMaxDynamicSharedMemorySize, SMEM_DYN);
        attr_set = true;
    }

    const int PREP_ELEMS = HID * 112 + N2 * HID;   // 188416
    prep_kernel<<<(PREP_ELEMS + 255) / 256, 256>>>((const int*)ei, W1l, W1r, W2l, W2r);
    count_kernel<<<(N_EDGES + 255) / 256, 256>>>(ei);
    scan_kernel<<<1, 640>>>();
    bucket_kernel<<<(N_EDGES + 255) / 256, 256>>>(ei);
    aggx_pack_kernel<<<(N_NODES * 32 + 255) / 256, 256>>>(x);
    mma_gemm_kernel<1><<<dim3(HID / 128, M_PAD / 128), 256, SMEM_DYN>>>(b1);
    mma_gemm_kernel<2><<<dim3(N2 / 128, M_PAD / 128), 256, SMEM_DYN>>>(nullptr);
    final_kernel<<<(N_NODES + 7) / 8, 256>>>(b2, out);
}

// round 11
// speedup vs baseline: 1.0170x; 1.0170x over previous
#include <cuda_runtime.h>
#include <cuda_bf16.h>
#include <cstdint>

#define N_NODES 10000
#define M_PAD   10112     // 79 tiles of 128
#define N_EDGES 160000
#define F0      50
#define HID     512
#define F2      121
#define N2      256
#define KA1     256
#define KB1     384
#define KA2     1024
#define KB2     1536

// ---------------- scratch (device globals; zero-initialized) -----------------
__device__ int   g_is64;
__device__ __align__(16) int   g_deg[N_NODES + 16];
__device__ __align__(16) int   g_rowstart[N_NODES + 16];
__device__ __align__(16) int   g_cursor[N_NODES + 16];
__device__ __align__(16) float g_invdeg[N_NODES + 16];
__device__ int   g_esrc[N_EDGES];
__device__ __align__(16) __nv_bfloat16 g_a1[(size_t)M_PAD * KA1];
__device__ __align__(16) __nv_bfloat16 g_b1p[(size_t)HID * KB1];
__device__ __align__(16) __nv_bfloat16 g_a2[(size_t)M_PAD * KA2];
__device__ __align__(16) __nv_bfloat16 g_b2p[(size_t)N2 * KB2];
__device__ __align__(16) float g_qr[(size_t)M_PAD * N2];            // [q | r | pad]

// ---------------- PTX helpers -------------------------------------------------
__device__ __forceinline__ uint32_t smem_u32(const void* p) {
    uint32_t a;
    asm("{ .reg .u64 t; cvta.to.shared.u64 t, %1; cvt.u32.u64 %0, t; }" : "=r"(a) : "l"(p));
    return a;
}
#define CP16(dst, src) \
    asm volatile("cp.async.cg.shared.global [%0], [%1], 16;" :: "r"(dst), "l"(src) : "memory")
#define CP_COMMIT() asm volatile("cp.async.commit_group;" ::: "memory")
#define CP_WAIT(n)  asm volatile("cp.async.wait_group %0;" :: "n"(n) : "memory")
#define LDSM_X4(r0, r1, r2, r3, addr) \
    asm volatile("ldmatrix.sync.aligned.m8n8.x4.shared.b16 {%0,%1,%2,%3}, [%4];" \
                 : "=r"(r0), "=r"(r1), "=r"(r2), "=r"(r3) : "r"(addr))
#define LDSM_X2(r0, r1, addr) \
    asm volatile("ldmatrix.sync.aligned.m8n8.x2.shared.b16 {%0,%1}, [%2];" \
                 : "=r"(r0), "=r"(r1) : "r"(addr))

__device__ __forceinline__ void mma16816(float* d, const uint32_t* a, const uint32_t* b) {
    asm volatile(
        "mma.sync.aligned.m16n8k16.row.col.f32.bf16.bf16.f32 "
        "{%0,%1,%2,%3}, {%4,%5,%6,%7}, {%8,%9}, {%0,%1,%2,%3};"
        : "+f"(d[0]), "+f"(d[1]), "+f"(d[2]), "+f"(d[3])
        : "r"(a[0]), "r"(a[1]), "r"(a[2]), "r"(a[3]), "r"(b[0]), "r"(b[1]));
}

// ---------------- hi/lo helpers ----------------------------------------------
__device__ __forceinline__ void hilo(float v, __nv_bfloat16& h, __nv_bfloat16& l) {
    h = __float2bfloat16_rn(v);
    l = __float2bfloat16_rn(v - __bfloat162float(h));
}

// Per-thread edge-index dtype detect: int64 data (<2^31) has zero odd words;
// int32 data has random nonzero values there (P[all 8 zero] ~ 1e-32).
__device__ __forceinline__ int detect64(const int* __restrict__ ei32) {
    int nz = 0;
#pragma unroll
    for (int i = 1; i < 16; i += 2) nz |= (ei32[i] != 0);
    return !nz;
}

// ---------------- prep: dtype detect + degree count + weight packs -----------
// Requires g_deg == 0 at entry: true on first call (zero-init globals) and on
// later calls because mma_gemm_kernel<2> re-zeroes it each run.
__global__ void prep_kernel(const void* __restrict__ ei,
                            const float* __restrict__ W1l, const float* __restrict__ W1r,
                            const float* __restrict__ W2l, const float* __restrict__ W2r) {
    int idx = blockIdx.x * blockDim.x + threadIdx.x;
    const int* ei32 = (const int*)ei;
    if (blockIdx.x == 0 && threadIdx.x == 0) g_is64 = detect64(ei32);  // for later kernels
    // degree count (inline per-thread dtype detect to avoid g_is64 race)
    if (idx < N_EDGES) {
        int is64 = detect64(ei32);
        int dst = is64 ? (int)((const long long*)ei)[N_EDGES + idx]
                       : ei32[N_EDGES + idx];
        dst = min(max(dst, 0), N_NODES - 1);
        atomicAdd(&g_deg[dst], 1);
    }
    // weight packs
    if (idx < HID * 112) {
        int k = idx % 112, n = idx / 112;
        float v = 0.f;
        if (k < F0)            v = W1l[k * HID + n];
        else if (k < 2 * F0)   v = W1r[(k - F0) * HID + n];
        __nv_bfloat16 h, l; hilo(v, h, l);
        size_t rb = (size_t)n * KB1;
        g_b1p[rb + k] = h; g_b1p[rb + 128 + k] = l; g_b1p[rb + 256 + k] = h;
    } else {
        int i2 = idx - HID * 112;
        if (i2 < N2 * HID) {
            int k = i2 % HID, n = i2 / HID;
            float v = 0.f;
            if (n < F2)            v = W2l[k * F2 + n];
            else if (n < 2 * F2)   v = W2r[k * F2 + (n - F2)];
            __nv_bfloat16 h, l; hilo(v, h, l);
            size_t rb = (size_t)n * KB2;
            g_b2p[rb + k] = h; g_b2p[rb + 512 + k] = l; g_b2p[rb + 1024 + k] = h;
        }
    }
}

__device__ __forceinline__ int load_idx(const void* ei, int pos) {
    int v = g_is64 ? (int)((const long long*)ei)[pos] : ((const int*)ei)[pos];
    return min(max(v, 0), N_NODES - 1);
}

// Vectorized two-level shfl scan: 640 threads x 16 elems (int4), 3 barriers.
__global__ void scan_kernel() {
    const int CH = 16;
    __shared__ int s_w[32];
    int t = threadIdx.x, lane = t & 31, wid = t >> 5;
    int base = t * CH;
    int local[CH];
    int sum = 0;
    if (base < N_NODES) {
#pragma unroll
        for (int v4 = 0; v4 < 4; v4++) {
            int4 v = *reinterpret_cast<const int4*>(&g_deg[base + v4 * 4]);
            local[v4 * 4 + 0] = v.x; local[v4 * 4 + 1] = v.y;
            local[v4 * 4 + 2] = v.z; local[v4 * 4 + 3] = v.w;
            sum += v.x + v.y + v.z + v.w;
        }
    } else {
#pragma unroll
        for (int i = 0; i < CH; i++) local[i] = 0;
    }
    if (t < 32) s_w[t] = 0;
    __syncthreads();
    int incl = sum;
#pragma unroll
    for (int off = 1; off < 32; off <<= 1) {
        int v = __shfl_up_sync(0xFFFFFFFFu, incl, off);
        if (lane >= off) incl += v;
    }
    if (lane == 31) s_w[wid] = incl;
    __syncthreads();
    if (wid == 0) {
        int v = s_w[lane];
        int wi = v;
#pragma unroll
        for (int off = 1; off < 32; off <<= 1) {
            int u = __shfl_up_sync(0xFFFFFFFFu, wi, off);
            if (lane >= off) wi += u;
        }
        s_w[lane] = wi - v;
    }
    __syncthreads();
    if (base >= N_NODES) return;
    int excl = s_w[wid] + (incl - sum);
#pragma unroll
    for (int v4 = 0; v4 < 4; v4++) {
        int4 rs; float4 iv;
        int d0 = local[v4 * 4 + 0], d1 = local[v4 * 4 + 1];
        int d2 = local[v4 * 4 + 2], d3 = local[v4 * 4 + 3];
        rs.x = excl;            rs.y = excl + d0;
        rs.z = excl + d0 + d1;  rs.w = excl + d0 + d1 + d2;
        excl += d0 + d1 + d2 + d3;
        iv.x = 1.0f / (float)(d0 > 1 ? d0 : 1);
        iv.y = 1.0f / (float)(d1 > 1 ? d1 : 1);
        iv.z = 1.0f / (float)(d2 > 1 ? d2 : 1);
        iv.w = 1.0f / (float)(d3 > 1 ? d3 : 1);
        *reinterpret_cast<int4*>(&g_rowstart[base + v4 * 4]) = rs;
        *reinterpret_cast<int4*>(&g_cursor[base + v4 * 4])   = rs;
        *reinterpret_cast<float4*>(&g_invdeg[base + v4 * 4]) = iv;
    }
}

__global__ void bucket_kernel(const void* __restrict__ ei) {
    int e = blockIdx.x * blockDim.x + threadIdx.x;
    if (e < N_EDGES) {
        int dst = load_idx(ei, N_EDGES + e);
        int pos = atomicAdd(&g_cursor[dst], 1);
        pos = min(max(pos, 0), N_EDGES - 1);
        g_esrc[pos] = load_idx(ei, e);
    }
}

// ---------------- layer-1 aggregation + A1 pack (2 panels: hi | lo) ----------
__global__ void aggx_pack_kernel(const float* __restrict__ x) {
    int gw = (blockIdx.x * blockDim.x + threadIdx.x) >> 5;
    int lane = threadIdx.x & 31;
    if (gw >= N_NODES) return;
    int beg = g_rowstart[gw];
    int d   = g_cursor[gw] - beg;
    float s0 = 0.f, s1 = 0.f;
    int i = 0;
    for (; i + 4 <= d; i += 4) {
        int sa = g_esrc[beg + i],     sb = g_esrc[beg + i + 1];
        int sc = g_esrc[beg + i + 2], sd = g_esrc[beg + i + 3];
        const float* xa = x + sa * F0;
        const float* xb = x + sb * F0;
        const float* xc = x + sc * F0;
        const float* xd = x + sd * F0;
        s0 += xa[lane] + xb[lane] + xc[lane] + xd[lane];
        if (lane < F0 - 32)
            s1 += xa[lane + 32] + xb[lane + 32] + xc[lane + 32] + xd[lane + 32];
    }
    for (; i < d; i++) {
        const float* xa = x + g_esrc[beg + i] * F0;
        s0 += xa[lane];
        if (lane < F0 - 32) s1 += xa[lane + 32];
    }
    float inv = g_invdeg[gw];
    const float* xs = x + gw * F0;
    size_t rb = (size_t)gw * KA1;
    __nv_bfloat16 h, l;
#define WR_A1(j, v) do { hilo((v), h, l); g_a1[rb + (j)] = h; g_a1[rb + 128 + (j)] = l; } while (0)
    WR_A1(lane, s0 * inv);
    if (lane < F0 - 32) WR_A1(lane + 32, s1 * inv);
    WR_A1(F0 + lane, xs[lane]);
    if (lane < F0 - 32) WR_A1(F0 + lane + 32, xs[lane + 32]);
#undef WR_A1
}

// ---------------- mma.sync GEMM: C[128x128 tile] = A B^T ---------------------
#define BK      64
#define LDPAD   72        // bf16 elems per smem row (64 + 8 pad) = 144B
#define ROWB    (LDPAD * 2)
#define TILE_B  (128 * ROWB)        // 18432 bytes per operand per stage

template <int MODE>
__global__ void __launch_bounds__(256) mma_gemm_kernel(const float* __restrict__ bias) {
    constexpr int C  = (MODE == 1) ? 6 : 24;
    constexpr int KA = (MODE == 1) ? KA1 : KA2;
    constexpr int KB = (MODE == 1) ? KB1 : KB2;
    const __nv_bfloat16* Ag = (MODE == 1) ? g_a1 : g_a2;
    const __nv_bfloat16* Bg = (MODE == 1) ? g_b1p : g_b2p;

    // MODE 2 re-zeroes g_deg for the NEXT kernel_launch call (prep requires
    // zeroed degrees; nothing after gemm2 reads g_deg).
    if (MODE == 2) {
        int gid = (blockIdx.y * gridDim.x + blockIdx.x) * blockDim.x + threadIdx.x;
        if (gid < N_NODES) g_deg[gid] = 0;
    }

    extern __shared__ __align__(16) char dsm[];
    uint32_t sb = smem_u32(dsm);

    int tid = threadIdx.x, wid = tid >> 5, lane = tid & 31;
    int wm = wid & 1, wn = wid >> 1;       // warp grid 2 (M) x 4 (N)
    int mbase = blockIdx.y * 128, nbase = blockIdx.x * 128;

    float acc[4][4][4];
#pragma unroll
    for (int i = 0; i < 4; i++)
#pragma unroll
        for (int j = 0; j < 4; j++)
#pragma unroll
            for (int k = 0; k < 4; k++) acc[i][j][k] = 0.f;

    uint32_t a_off[4], b_off[4];
#pragma unroll
    for (int mi = 0; mi < 4; mi++)
        a_off[mi] = (uint32_t)(wm * 64 + mi * 16 + (lane & 15)) * ROWB + (uint32_t)(lane >> 4) * 16u;
#pragma unroll
    for (int ni = 0; ni < 4; ni++)
        b_off[ni] = (uint32_t)(wn * 32 + ni * 8 + (lane & 7)) * ROWB + (uint32_t)((lane >> 3) & 1) * 16u;

    auto aoff_of = [](int c) -> int {
        if (MODE == 1) {
            const int m[6] = {0, 64, 0, 64, 128, 192};
            return m[c];
        } else {
            return (c < 16) ? (c & 7) * 64 : 512 + (c - 16) * 64;
        }
    };

    auto load_chunk = [&](int c, int s) {
        uint32_t da = sb + s * 2 * TILE_B;
        uint32_t db = da + TILE_B;
        const __nv_bfloat16* asrc = Ag + (size_t)mbase * KA + aoff_of(c);
        const __nv_bfloat16* bsrc = Bg + (size_t)nbase * KB + c * BK;
#pragma unroll
        for (int i = 0; i < 4; i++) {
            int seg = tid + i * 256;
            int row = seg >> 3, s16 = seg & 7;
            uint32_t off = row * ROWB + s16 * 16;
            CP16(da + off, asrc + (size_t)row * KA + s16 * 8);
            CP16(db + off, bsrc + (size_t)row * KB + s16 * 8);
        }
        CP_COMMIT();
    };

    load_chunk(0, 0);

    for (int c = 0; c < C; ++c) {
        int s = c & 1;
        if (c + 1 < C) { load_chunk(c + 1, s ^ 1); CP_WAIT(1); }
        else           { CP_WAIT(0); }
        __syncthreads();

        uint32_t As = sb + s * 2 * TILE_B;
        uint32_t Bs = As + TILE_B;
#pragma unroll
        for (int k16 = 0; k16 < BK / 16; ++k16) {
            uint32_t afr[4][4], bfr[4][2];
#pragma unroll
            for (int mi = 0; mi < 4; mi++)
                LDSM_X4(afr[mi][0], afr[mi][1], afr[mi][2], afr[mi][3],
                        As + a_off[mi] + k16 * 32u);
#pragma unroll
            for (int ni = 0; ni < 4; ni++)
                LDSM_X2(bfr[ni][0], bfr[ni][1], Bs + b_off[ni] + k16 * 32u);
#pragma unroll
            for (int mi = 0; mi < 4; mi++)
#pragma unroll
                for (int ni = 0; ni < 4; ni++)
                    mma16816(acc[mi][ni], afr[mi], bfr[ni]);
        }
        __syncthreads();
    }

    // ---- epilogue ----
    int lr = lane >> 2, lc = lane & 3;
#pragma unroll
    for (int mi = 0; mi < 4; mi++) {
        int row0 = mbase + wm * 64 + mi * 16 + lr;
        int row1 = row0 + 8;
#pragma unroll
        for (int ni = 0; ni < 4; ni++) {
            int col0 = nbase + wn * 32 + ni * 8 + lc * 2;
            float* d = acc[mi][ni];
            if (MODE == 1) {
                float bb0 = bias[col0], bb1 = bias[col0 + 1];
#pragma unroll
                for (int hf = 0; hf < 2; hf++) {
                    int r = hf ? row1 : row0;
                    if (r >= N_NODES) continue;
                    float v0 = fmaxf(d[hf * 2 + 0] + bb0, 0.f);
                    float v1 = fmaxf(d[hf * 2 + 1] + bb1, 0.f);
                    __nv_bfloat16 h0, l0, h1, l1;
                    hilo(v0, h0, l0); hilo(v1, h1, l1);
                    size_t rb = (size_t)r * KA2;
                    __nv_bfloat162 hp; hp.x = h0; hp.y = h1;
                    __nv_bfloat162 lp; lp.x = l0; lp.y = l1;
                    *reinterpret_cast<__nv_bfloat162*>(&g_a2[rb + col0]) = hp;
                    *reinterpret_cast<__nv_bfloat162*>(&g_a2[rb + 512 + col0]) = lp;
                }
            } else {
                if (row0 < N_NODES)
                    *reinterpret_cast<float2*>(&g_qr[(size_t)row0 * N2 + col0]) =
                        make_float2(d[0], d[1]);
                if (row1 < N_NODES)
                    *reinterpret_cast<float2*>(&g_qr[(size_t)row1 * N2 + col0]) =
                        make_float2(d[2], d[3]);
            }
        }
    }
}

// ---------------- final: out = mean_agg(q) + r + b2 --------------------------
__global__ void final_kernel(const float* __restrict__ b2, float* __restrict__ out) {
    int gw = (blockIdx.x * blockDim.x + threadIdx.x) >> 5;
    int lane = threadIdx.x & 31;
    if (gw >= N_NODES) return;
    int beg = g_rowstart[gw];
    int d   = g_cursor[gw] - beg;
    int j4 = lane * 4;
    float4 acc = make_float4(0.f, 0.f, 0.f, 0.f);
    int i = 0;
    for (; i + 4 <= d; i += 4) {
        int s0 = g_esrc[beg + i],     s1 = g_esrc[beg + i + 1];
        int s2 = g_esrc[beg + i + 2], s3 = g_esrc[beg + i + 3];
        float4 v0 = *reinterpret_cast<const float4*>(g_qr + (size_t)s0 * N2 + j4);
        float4 v1 = *reinterpret_cast<const float4*>(g_qr + (size_t)s1 * N2 + j4);
        float4 v2 = *reinterpret_cast<const float4*>(g_qr + (size_t)s2 * N2 + j4);
        float4 v3 = *reinterpret_cast<const float4*>(g_qr + (size_t)s3 * N2 + j4);
        acc.x += v0.x + v1.x + v2.x + v3.x;
        acc.y += v0.y + v1.y + v2.y + v3.y;
        acc.z += v0.z + v1.z + v2.z + v3.z;
        acc.w += v0.w + v1.w + v2.w + v3.w;
    }
    for (; i < d; i++) {
        int s0 = g_esrc[beg + i];
        float4 v0 = *reinterpret_cast<const float4*>(g_qr + (size_t)s0 * N2 + j4);
        acc.x += v0.x; acc.y += v0.y; acc.z += v0.z; acc.w += v0.w;
    }
    float inv = g_invdeg[gw];
    const float* rrow = g_qr + (size_t)gw * N2 + F2;
    float* orow = out + (size_t)gw * F2;
    float av[4] = {acc.x, acc.y, acc.z, acc.w};
#pragma unroll
    for (int c = 0; c < 4; c++) {
        int jj = j4 + c;
        if (jj < F2) orow[jj] = av[c] * inv + rrow[jj] + b2[jj];
    }
}

// ---------------- launch ------------------------------------------------------
extern "C" void kernel_launch(void* const* d_in, const int* in_sizes, int n_in,
                              void* d_out, int out_size) {
    const float* x   = (const float*)d_in[0];
    const void*  ei  = d_in[1];
    const float* W1l = (const float*)d_in[2];
    const float* W1r = (const float*)d_in[3];
    const float* b1  = (const float*)d_in[4];
    const float* W2l = (const float*)d_in[5];
    const float* W2r = (const float*)d_in[6];
    const float* b2  = (const float*)d_in[7];
    float*       out = (float*)d_out;

    const int SMEM_DYN = 4 * TILE_B;   // 73728 bytes: 2 stages x (A + B)
    static bool attr_set = false;
    if (!attr_set) {
        cudaFuncSetAttribute(mma_gemm_kernel<1>, cudaFuncAttributeMaxDynamicSharedMemorySize, SMEM_DYN);
        cudaFuncSetAttribute(mma_gemm_kernel<2>, cudaFuncAttributeMaxDynamicSharedMemorySize, SMEM_DYN);
        attr_set = true;
    }

    const int PREP_ELEMS = HID * 112 + N2 * HID;   // 188416 >= N_EDGES
    prep_kernel<<<(PREP_ELEMS + 255) / 256, 256>>>(ei, W1l, W1r, W2l, W2r);
    scan_kernel<<<1, 640>>>();
    bucket_kernel<<<(N_EDGES + 255) / 256, 256>>>(ei);
    aggx_pack_kernel<<<(N_NODES * 32 + 255) / 256, 256>>>(x);
    mma_gemm_kernel<1><<<dim3(HID / 128, M_PAD / 128), 256, SMEM_DYN>>>(b1);
    mma_gemm_kernel<2><<<dim3(N2 / 128, M_PAD / 128), 256, SMEM_DYN>>>(nullptr);
    final_kernel<<<(N_NODES + 7) / 8, 256>>>(b2, out);
}

// round 13
// speedup vs baseline: 1.4783x; 1.4536x over previous
#include <cuda_runtime.h>
#include <cuda_bf16.h>
#include <cuda_fp16.h>
#include <cstdint>

#define N_NODES 10000
#define M_PAD   10112     // 79 tiles of 128
#define N_EDGES 160000
#define F0      50
#define HID     512
#define F2      121
#define N2      256
#define KA1     256       // layer-1 A: 2 panels [hi|lo] bf16
#define KB1     384       // layer-1 B: 3 panels [hi|lo|hi] bf16
#define KA2     512       // layer-2 A: single fp16 panel
#define KB2     512       // layer-2 B: single fp16 panel

// ---------------- scratch (device globals; zero-initialized) -----------------
__device__ int   g_is64;
__device__ __align__(16) int   g_deg[N_NODES + 16];
__device__ __align__(16) int   g_rowstart[N_NODES + 16];
__device__ __align__(16) int   g_cursor[N_NODES + 16];
__device__ __align__(16) float g_invdeg[N_NODES + 16];
__device__ int   g_esrc[N_EDGES];
__device__ __align__(16) __nv_bfloat16 g_a1[(size_t)M_PAD * KA1];
__device__ __align__(16) __nv_bfloat16 g_b1p[(size_t)HID * KB1];
__device__ __align__(16) __half g_a2h[(size_t)M_PAD * KA2];
__device__ __align__(16) __half g_b2p[(size_t)N2 * KB2];
__device__ __align__(16) float g_qr[(size_t)M_PAD * N2];            // [q | r | pad]

// ---------------- PTX helpers -------------------------------------------------
__device__ __forceinline__ uint32_t smem_u32(const void* p) {
    uint32_t a;
    asm("{ .reg .u64 t; cvta.to.shared.u64 t, %1; cvt.u32.u64 %0, t; }" : "=r"(a) : "l"(p));
    return a;
}
#define CP16(dst, src) \
    asm volatile("cp.async.cg.shared.global [%0], [%1], 16;" :: "r"(dst), "l"(src) : "memory")
#define CP_COMMIT() asm volatile("cp.async.commit_group;" ::: "memory")
#define CP_WAIT(n)  asm volatile("cp.async.wait_group %0;" :: "n"(n) : "memory")
#define LDSM_X4(r0, r1, r2, r3, addr) \
    asm volatile("ldmatrix.sync.aligned.m8n8.x4.shared.b16 {%0,%1,%2,%3}, [%4];" \
                 : "=r"(r0), "=r"(r1), "=r"(r2), "=r"(r3) : "r"(addr))
#define LDSM_X2(r0, r1, addr) \
    asm volatile("ldmatrix.sync.aligned.m8n8.x2.shared.b16 {%0,%1}, [%2];" \
                 : "=r"(r0), "=r"(r1) : "r"(addr))

__device__ __forceinline__ void mma_bf16(float* d, const uint32_t* a, const uint32_t* b) {
    asm volatile(
        "mma.sync.aligned.m16n8k16.row.col.f32.bf16.bf16.f32 "
        "{%0,%1,%2,%3}, {%4,%5,%6,%7}, {%8,%9}, {%0,%1,%2,%3};"
        : "+f"(d[0]), "+f"(d[1]), "+f"(d[2]), "+f"(d[3])
        : "r"(a[0]), "r"(a[1]), "r"(a[2]), "r"(a[3]), "r"(b[0]), "r"(b[1]));
}
__device__ __forceinline__ void mma_fp16(float* d, const uint32_t* a, const uint32_t* b) {
    asm volatile(
        "mma.sync.aligned.m16n8k16.row.col.f32.f16.f16.f32 "
        "{%0,%1,%2,%3}, {%4,%5,%6,%7}, {%8,%9}, {%0,%1,%2,%3};"
        : "+f"(d[0]), "+f"(d[1]), "+f"(d[2]), "+f"(d[3])
        : "r"(a[0]), "r"(a[1]), "r"(a[2]), "r"(a[3]), "r"(b[0]), "r"(b[1]));
}

// ---------------- hi/lo helpers ----------------------------------------------
__device__ __forceinline__ void hilo(float v, __nv_bfloat16& h, __nv_bfloat16& l) {
    h = __float2bfloat16_rn(v);
    l = __float2bfloat16_rn(v - __bfloat162float(h));
}

// Per-thread edge-index dtype detect: int64 data (<2^31) has zero odd words.
__device__ __forceinline__ int detect64(const int* __restrict__ ei32) {
    int nz = 0;
#pragma unroll
    for (int i = 1; i < 16; i += 2) nz |= (ei32[i] != 0);
    return !nz;
}

// ---------------- prep: dtype detect + degree count + weight packs -----------
// Requires g_deg == 0 at entry: true on first call (zero-init globals) and on
// later calls because mma_gemm_kernel<2> re-zeroes it each run.
__global__ void prep_kernel(const void* __restrict__ ei,
                            const float* __restrict__ W1l, const float* __restrict__ W1r,
                            const float* __restrict__ W2l, const float* __restrict__ W2r) {
    int idx = blockIdx.x * blockDim.x + threadIdx.x;
    const int* ei32 = (const int*)ei;
    if (blockIdx.x == 0 && threadIdx.x == 0) g_is64 = detect64(ei32);
    if (idx < N_EDGES) {
        int is64 = detect64(ei32);
        int dst = is64 ? (int)((const long long*)ei)[N_EDGES + idx]
                       : ei32[N_EDGES + idx];
        dst = min(max(dst, 0), N_NODES - 1);
        atomicAdd(&g_deg[dst], 1);
    }
    if (idx < HID * 112) {
        int k = idx % 112, n = idx / 112;
        float v = 0.f;
        if (k < F0)            v = W1l[k * HID + n];
        else if (k < 2 * F0)   v = W1r[(k - F0) * HID + n];
        __nv_bfloat16 h, l; hilo(v, h, l);
        size_t rb = (size_t)n * KB1;
        g_b1p[rb + k] = h; g_b1p[rb + 128 + k] = l; g_b1p[rb + 256 + k] = h;
    } else {
        int i2 = idx - HID * 112;
        if (i2 < N2 * HID) {
            int k = i2 % HID, n = i2 / HID;
            float v = 0.f;
            if (n < F2)            v = W2l[k * F2 + n];
            else if (n < 2 * F2)   v = W2r[k * F2 + (n - F2)];
            g_b2p[(size_t)n * KB2 + k] = __float2half_rn(v);
        }
    }
}

__device__ __forceinline__ int load_idx(const void* ei, int pos) {
    int v = g_is64 ? (int)((const long long*)ei)[pos] : ((const int*)ei)[pos];
    return min(max(v, 0), N_NODES - 1);
}

// Vectorized two-level shfl scan: 640 threads x 16 elems (int4), 3 barriers.
__global__ void scan_kernel() {
    const int CH = 16;
    __shared__ int s_w[32];
    int t = threadIdx.x, lane = t & 31, wid = t >> 5;
    int base = t * CH;
    int local[CH];
    int sum = 0;
    if (base < N_NODES) {
#pragma unroll
        for (int v4 = 0; v4 < 4; v4++) {
            int4 v = *reinterpret_cast<const int4*>(&g_deg[base + v4 * 4]);
            local[v4 * 4 + 0] = v.x; local[v4 * 4 + 1] = v.y;
            local[v4 * 4 + 2] = v.z; local[v4 * 4 + 3] = v.w;
            sum += v.x + v.y + v.z + v.w;
        }
    } else {
#pragma unroll
        for (int i = 0; i < CH; i++) local[i] = 0;
    }
    if (t < 32) s_w[t] = 0;
    __syncthreads();
    int incl = sum;
#pragma unroll
    for (int off = 1; off < 32; off <<= 1) {
        int v = __shfl_up_sync(0xFFFFFFFFu, incl, off);
        if (lane >= off) incl += v;
    }
    if (lane == 31) s_w[wid] = incl;
    __syncthreads();
    if (wid == 0) {
        int v = s_w[lane];
        int wi = v;
#pragma unroll
        for (int off = 1; off < 32; off <<= 1) {
            int u = __shfl_up_sync(0xFFFFFFFFu, wi, off);
            if (lane >= off) wi += u;
        }
        s_w[lane] = wi - v;
    }
    __syncthreads();
    if (base >= N_NODES) return;
    int excl = s_w[wid] + (incl - sum);
#pragma unroll
    for (int v4 = 0; v4 < 4; v4++) {
        int4 rs; float4 iv;
        int d0 = local[v4 * 4 + 0], d1 = local[v4 * 4 + 1];
        int d2 = local[v4 * 4 + 2], d3 = local[v4 * 4 + 3];
        rs.x = excl;            rs.y = excl + d0;
        rs.z = excl + d0 + d1;  rs.w = excl + d0 + d1 + d2;
        excl += d0 + d1 + d2 + d3;
        iv.x = 1.0f / (float)(d0 > 1 ? d0 : 1);
        iv.y = 1.0f / (float)(d1 > 1 ? d1 : 1);
        iv.z = 1.0f / (float)(d2 > 1 ? d2 : 1);
        iv.w = 1.0f / (float)(d3 > 1 ? d3 : 1);
        *reinterpret_cast<int4*>(&g_rowstart[base + v4 * 4]) = rs;
        *reinterpret_cast<int4*>(&g_cursor[base + v4 * 4])   = rs;
        *reinterpret_cast<float4*>(&g_invdeg[base + v4 * 4]) = iv;
    }
}

__global__ void bucket_kernel(const void* __restrict__ ei) {
    int e = blockIdx.x * blockDim.x + threadIdx.x;
    if (e < N_EDGES) {
        int dst = load_idx(ei, N_EDGES + e);
        int pos = atomicAdd(&g_cursor[dst], 1);
        pos = min(max(pos, 0), N_EDGES - 1);
        g_esrc[pos] = load_idx(ei, e);
    }
}

// ---------------- layer-1 aggregation + A1 pack (2 panels: hi | lo) ----------
__global__ void aggx_pack_kernel(const float* __restrict__ x) {
    int gw = (blockIdx.x * blockDim.x + threadIdx.x) >> 5;
    int lane = threadIdx.x & 31;
    if (gw >= N_NODES) return;
    int beg = g_rowstart[gw];
    int d   = g_cursor[gw] - beg;
    float s0 = 0.f, s1 = 0.f;
    int i = 0;
    for (; i + 4 <= d; i += 4) {
        int sa = g_esrc[beg + i],     sb = g_esrc[beg + i + 1];
        int sc = g_esrc[beg + i + 2], sd = g_esrc[beg + i + 3];
        const float* xa = x + sa * F0;
        const float* xb = x + sb * F0;
        const float* xc = x + sc * F0;
        const float* xd = x + sd * F0;
        s0 += xa[lane] + xb[lane] + xc[lane] + xd[lane];
        if (lane < F0 - 32)
            s1 += xa[lane + 32] + xb[lane + 32] + xc[lane + 32] + xd[lane + 32];
    }
    for (; i < d; i++) {
        const float* xa = x + g_esrc[beg + i] * F0;
        s0 += xa[lane];
        if (lane < F0 - 32) s1 += xa[lane + 32];
    }
    float inv = g_invdeg[gw];
    const float* xs = x + gw * F0;
    size_t rb = (size_t)gw * KA1;
    __nv_bfloat16 h, l;
#define WR_A1(j, v) do { hilo((v), h, l); g_a1[rb + (j)] = h; g_a1[rb + 128 + (j)] = l; } while (0)
    WR_A1(lane, s0 * inv);
    if (lane < F0 - 32) WR_A1(lane + 32, s1 * inv);
    WR_A1(F0 + lane, xs[lane]);
    if (lane < F0 - 32) WR_A1(F0 + lane + 32, xs[lane + 32]);
#undef WR_A1
}

// ---------------- mma.sync GEMM: C[128x128 tile] = A B^T ---------------------
#define BK      64
#define LDPAD   72        // 16-bit elems per smem row (64 + 8 pad) = 144B
#define ROWB    (LDPAD * 2)
#define TILE_B  (128 * ROWB)        // 18432 bytes per operand per stage

template <int MODE>
__global__ void __launch_bounds__(256) mma_gemm_kernel(const float* __restrict__ bias) {
    constexpr int C  = (MODE == 1) ? 6 : 8;
    constexpr int KA = (MODE == 1) ? KA1 : KA2;
    constexpr int KB = (MODE == 1) ? KB1 : KB2;
    const __nv_bfloat16* Ag = (MODE == 1) ? g_a1 : (const __nv_bfloat16*)g_a2h;
    const __nv_bfloat16* Bg = (MODE == 1) ? g_b1p : (const __nv_bfloat16*)g_b2p;

    // MODE 2 re-zeroes g_deg for the NEXT kernel_launch call.
    if (MODE == 2) {
        int gid = (blockIdx.y * gridDim.x + blockIdx.x) * blockDim.x + threadIdx.x;
        if (gid < N_NODES) g_deg[gid] = 0;
    }

    extern __shared__ __align__(16) char dsm[];
    uint32_t sb = smem_u32(dsm);

    int tid = threadIdx.x, wid = tid >> 5, lane = tid & 31;
    int wm = wid & 1, wn = wid >> 1;       // warp grid 2 (M) x 4 (N)
    int mbase = blockIdx.y * 128, nbase = blockIdx.x * 128;

    float acc[4][4][4];
#pragma unroll
    for (int i = 0; i < 4; i++)
#pragma unroll
        for (int j = 0; j < 4; j++)
#pragma unroll
            for (int k = 0; k < 4; k++) acc[i][j][k] = 0.f;

    uint32_t a_off[4], b_off[4];
#pragma unroll
    for (int mi = 0; mi < 4; mi++)
        a_off[mi] = (uint32_t)(wm * 64 + mi * 16 + (lane & 15)) * ROWB + (uint32_t)(lane >> 4) * 16u;
#pragma unroll
    for (int ni = 0; ni < 4; ni++)
        b_off[ni] = (uint32_t)(wn * 32 + ni * 8 + (lane & 7)) * ROWB + (uint32_t)((lane >> 3) & 1) * 16u;

    auto aoff_of = [](int c) -> int {
        if (MODE == 1) {
            const int m[6] = {0, 64, 0, 64, 128, 192};
            return m[c];
        } else {
            return c * 64;
        }
    };

    auto load_chunk = [&](int c, int s) {
        uint32_t da = sb + s * 2 * TILE_B;
        uint32_t db = da + TILE_B;
        const __nv_bfloat16* asrc = Ag + (size_t)mbase * KA + aoff_of(c);
        const __nv_bfloat16* bsrc = Bg + (size_t)nbase * KB + c * BK;
#pragma unroll
        for (int i = 0; i < 4; i++) {
            int seg = tid + i * 256;
            int row = seg >> 3, s16 = seg & 7;
            uint32_t off = row * ROWB + s16 * 16;
            CP16(da + off, asrc + (size_t)row * KA + s16 * 8);
            CP16(db + off, bsrc + (size_t)row * KB + s16 * 8);
        }
        CP_COMMIT();
    };

    load_chunk(0, 0);

    for (int c = 0; c < C; ++c) {
        int s = c & 1;
        if (c + 1 < C) { load_chunk(c + 1, s ^ 1); CP_WAIT(1); }
        else           { CP_WAIT(0); }
        __syncthreads();

        uint32_t As = sb + s * 2 * TILE_B;
        uint32_t Bs = As + TILE_B;
#pragma unroll
        for (int k16 = 0; k16 < BK / 16; ++k16) {
            uint32_t afr[4][4], bfr[4][2];
#pragma unroll
            for (int mi = 0; mi < 4; mi++)
                LDSM_X4(afr[mi][0], afr[mi][1], afr[mi][2], afr[mi][3],
                        As + a_off[mi] + k16 * 32u);
#pragma unroll
            for (int ni = 0; ni < 4; ni++)
                LDSM_X2(bfr[ni][0], bfr[ni][1], Bs + b_off[ni] + k16 * 32u);
#pragma unroll
            for (int mi = 0; mi < 4; mi++)
#pragma unroll
                for (int ni = 0; ni < 4; ni++) {
                    if (MODE == 1) mma_bf16(acc[mi][ni], afr[mi], bfr[ni]);
                    else           mma_fp16(acc[mi][ni], afr[mi], bfr[ni]);
                }
        }
        __syncthreads();
    }

    // ---- epilogue ----
    int lr = lane >> 2, lc = lane & 3;
#pragma unroll
    for (int mi = 0; mi < 4; mi++) {
        int row0 = mbase + wm * 64 + mi * 16 + lr;
        int row1 = row0 + 8;
#pragma unroll
        for (int ni = 0; ni < 4; ni++) {
            int col0 = nbase + wn * 32 + ni * 8 + lc * 2;
            float* d = acc[mi][ni];
            if (MODE == 1) {
                float bb0 = bias[col0], bb1 = bias[col0 + 1];
#pragma unroll
                for (int hf = 0; hf < 2; hf++) {
                    int r = hf ? row1 : row0;
                    if (r >= N_NODES) continue;
                    float v0 = fmaxf(d[hf * 2 + 0] + bb0, 0.f);
                    float v1 = fmaxf(d[hf * 2 + 1] + bb1, 0.f);
                    *reinterpret_cast<__half2*>(&g_a2h[(size_t)r * KA2 + col0]) =
                        __floats2half2_rn(v0, v1);
                }
            } else {
                if (row0 < N_NODES)
                    *reinterpret_cast<float2*>(&g_qr[(size_t)row0 * N2 + col0]) =
                        make_float2(d[0], d[1]);
                if (row1 < N_NODES)
                    *reinterpret_cast<float2*>(&g_qr[(size_t)row1 * N2 + col0]) =
                        make_float2(d[2], d[3]);
            }
        }
    }
}

// ---------------- final: out = mean_agg(q) + r + b2 --------------------------
__global__ void final_kernel(const float* __restrict__ b2, float* __restrict__ out) {
    int gw = (blockIdx.x * blockDim.x + threadIdx.x) >> 5;
    int lane = threadIdx.x & 31;
    if (gw >= N_NODES) return;
    int beg = g_rowstart[gw];
    int d   = g_cursor[gw] - beg;
    int j4 = lane * 4;
    float4 acc = make_float4(0.f, 0.f, 0.f, 0.f);
    int i = 0;
    for (; i + 4 <= d; i += 4) {
        int s0 = g_esrc[beg + i],     s1 = g_esrc[beg + i + 1];
        int s2 = g_esrc[beg + i + 2], s3 = g_esrc[beg + i + 3];
        float4 v0 = *reinterpret_cast<const float4*>(g_qr + (size_t)s0 * N2 + j4);
        float4 v1 = *reinterpret_cast<const float4*>(g_qr + (size_t)s1 * N2 + j4);
        float4 v2 = *reinterpret_cast<const float4*>(g_qr + (size_t)s2 * N2 + j4);
        float4 v3 = *reinterpret_cast<const float4*>(g_qr + (size_t)s3 * N2 + j4);
        acc.x += v0.x + v1.x + v2.x + v3.x;
        acc.y += v0.y + v1.y + v2.y + v3.y;
        acc.z += v0.z + v1.z + v2.z + v3.z;
        acc.w += v0.w + v1.w + v2.w + v3.w;
    }
    for (; i < d; i++) {
        int s0 = g_esrc[beg + i];
        float4 v0 = *reinterpret_cast<const float4*>(g_qr + (size_t)s0 * N2 + j4);
        acc.x += v0.x; acc.y += v0.y; acc.z += v0.z; acc.w += v0.w;
    }
    float inv = g_invdeg[gw];
    const float* rrow = g_qr + (size_t)gw * N2 + F2;
    float* orow = out + (size_t)gw * F2;
    float av[4] = {acc.x, acc.y, acc.z, acc.w};
#pragma unroll
    for (int c = 0; c < 4; c++) {
        int jj = j4 + c;
        if (jj < F2) orow[jj] = av[c] * inv + rrow[jj] + b2[jj];
    }
}

// ---------------- launch ------------------------------------------------------
extern "C" void kernel_launch(void* const* d_in, const int* in_sizes, int n_in,
                              void* d_out, int out_size) {
    const float* x   = (const float*)d_in[0];
    const void*  ei  = d_in[1];
    const float* W1l = (const float*)d_in[2];
    const float* W1r = (const float*)d_in[3];
    const float* b1  = (const float*)d_in[4];
    const float* W2l = (const float*)d_in[5];
    const float* W2r = (const float*)d_in[6];
    const float* b2  = (const float*)d_in[7];
    float*       out = (float*)d_out;

    const int SMEM_DYN = 4 * TILE_B;   // 73728 bytes: 2 stages x (A + B)
    static bool attr_set = false;
    if (!attr_set) {
        cudaFuncSetAttribute(mma_gemm_kernel<1>, cudaFuncAttributeMaxDynamicSharedMemorySize, SMEM_DYN);
        cudaFuncSetAttribute(mma_gemm_kernel<2>, cudaFuncAttributeMaxDynamicSharedMemorySize, SMEM_DYN);
        attr_set = true;
    }

    const int PREP_ELEMS = HID * 112 + N2 * HID;   // 188416 >= N_EDGES
    prep_kernel<<<(PREP_ELEMS + 255) / 256, 256>>>(ei, W1l, W1r, W2l, W2r);
    scan_kernel<<<1, 640>>>();
    bucket_kernel<<<(N_EDGES + 255) / 256, 256>>>(ei);
    aggx_pack_kernel<<<(N_NODES * 32 + 255) / 256, 256>>>(x);
    mma_gemm_kernel<1><<<dim3(HID / 128, M_PAD / 128), 256, SMEM_DYN>>>(b1);
    mma_gemm_kernel<2><<<dim3(N2 / 128, M_PAD / 128), 256, SMEM_DYN>>>(nullptr);
    final_kernel<<<(N_NODES + 7) / 8, 256>>>(b2, out);
}

// round 16
// speedup vs baseline: 1.6994x; 1.1496x over previous
#include <cuda_runtime.h>
#include <cuda_bf16.h>
#include <cuda_fp16.h>
#include <cstdint>

#define N_NODES 10000
#define M_PAD   10112     // 79 tiles of 128
#define N_EDGES 160000
#define F0      50
#define HID     512
#define F2      121
#define N2      256
#define KA1     128       // layer-1: single fp16 panel ([agg|self|pad] = 100 -> 128)
#define KB1     128
#define KA2     512       // layer-2: single fp16 panel
#define KB2     512

// ---------------- scratch (device globals; zero-initialized) -----------------
// pad columns of g_a1h/g_b1h (k in [100,128)) are never written -> stay zero.
__device__ int   g_is64;
__device__ __align__(16) int   g_deg[N_NODES + 16];
__device__ __align__(16) int   g_rowstart[N_NODES + 16];
__device__ __align__(16) int   g_cursor[N_NODES + 16];
__device__ __align__(16) float g_invdeg[N_NODES + 16];
__device__ int   g_esrc[N_EDGES];
__device__ __align__(16) __half g_a1h[(size_t)M_PAD * KA1];
__device__ __align__(16) __half g_b1h[(size_t)HID * KB1];
__device__ __align__(16) __half g_a2h[(size_t)M_PAD * KA2];
__device__ __align__(16) __half g_b2p[(size_t)N2 * KB2];
__device__ __align__(16) float g_qr[(size_t)M_PAD * N2];            // [q | r | pad]

// ---------------- PTX helpers -------------------------------------------------
__device__ __forceinline__ uint32_t smem_u32(const void* p) {
    uint32_t a;
    asm("{ .reg .u64 t; cvta.to.shared.u64 t, %1; cvt.u32.u64 %0, t; }" : "=r"(a) : "l"(p));
    return a;
}
#define CP16(dst, src) \
    asm volatile("cp.async.cg.shared.global [%0], [%1], 16;" :: "r"(dst), "l"(src) : "memory")
#define CP_COMMIT() asm volatile("cp.async.commit_group;" ::: "memory")
#define CP_WAIT(n)  asm volatile("cp.async.wait_group %0;" :: "n"(n) : "memory")
#define LDSM_X4(r0, r1, r2, r3, addr) \
    asm volatile("ldmatrix.sync.aligned.m8n8.x4.shared.b16 {%0,%1,%2,%3}, [%4];" \
                 : "=r"(r0), "=r"(r1), "=r"(r2), "=r"(r3) : "r"(addr))
#define LDSM_X2(r0, r1, addr) \
    asm volatile("ldmatrix.sync.aligned.m8n8.x2.shared.b16 {%0,%1}, [%2];" \
                 : "=r"(r0), "=r"(r1) : "r"(addr))

__device__ __forceinline__ void mma_fp16(float* d, const uint32_t* a, const uint32_t* b) {
    asm volatile(
        "mma.sync.aligned.m16n8k16.row.col.f32.f16.f16.f32 "
        "{%0,%1,%2,%3}, {%4,%5,%6,%7}, {%8,%9}, {%0,%1,%2,%3};"
        : "+f"(d[0]), "+f"(d[1]), "+f"(d[2]), "+f"(d[3])
        : "r"(a[0]), "r"(a[1]), "r"(a[2]), "r"(a[3]), "r"(b[0]), "r"(b[1]));
}

// Per-thread edge-index dtype detect: int64 data (<2^31) has zero odd words.
__device__ __forceinline__ int detect64(const int* __restrict__ ei32) {
    int nz = 0;
#pragma unroll
    for (int i = 1; i < 16; i += 2) nz |= (ei32[i] != 0);
    return !nz;
}

// ---------------- prep: dtype detect + degree count + weight packs -----------
// Requires g_deg == 0 at entry: true on first call (zero-init globals) and on
// later calls because mma_gemm_kernel<2> re-zeroes it each run.
__global__ void prep_kernel(const void* __restrict__ ei,
                            const float* __restrict__ W1l, const float* __restrict__ W1r,
                            const float* __restrict__ W2l, const float* __restrict__ W2r) {
    int idx = blockIdx.x * blockDim.x + threadIdx.x;
    const int* ei32 = (const int*)ei;
    if (blockIdx.x == 0 && threadIdx.x == 0) g_is64 = detect64(ei32);
    if (idx < N_EDGES) {
        int is64 = detect64(ei32);
        int dst = is64 ? (int)((const long long*)ei)[N_EDGES + idx]
                       : ei32[N_EDGES + idx];
        dst = min(max(dst, 0), N_NODES - 1);
        atomicAdd(&g_deg[dst], 1);
    }
    if (idx < HID * 100) {
        int k = idx % 100, n = idx / 100;
        float v = (k < F0) ? W1l[k * HID + n] : W1r[(k - F0) * HID + n];
        g_b1h[(size_t)n * KB1 + k] = __float2half_rn(v);
    } else {
        int i2 = idx - HID * 100;
        if (i2 < N2 * HID) {
            int k = i2 % HID, n = i2 / HID;
            float v = 0.f;
            if (n < F2)            v = W2l[k * F2 + n];
            else if (n < 2 * F2)   v = W2r[k * F2 + (n - F2)];
            g_b2p[(size_t)n * KB2 + k] = __float2half_rn(v);
        }
    }
}

__device__ __forceinline__ int load_idx(const void* ei, int pos) {
    int v = g_is64 ? (int)((const long long*)ei)[pos] : ((const int*)ei)[pos];
    return min(max(v, 0), N_NODES - 1);
}

// Vectorized two-level shfl scan: 640 threads x 16 elems (int4), 3 barriers.
__global__ void scan_kernel() {
    const int CH = 16;
    __shared__ int s_w[32];
    int t = threadIdx.x, lane = t & 31, wid = t >> 5;
    int base = t * CH;
    int local[CH];
    int sum = 0;
    if (base < N_NODES) {
#pragma unroll
        for (int v4 = 0; v4 < 4; v4++) {
            int4 v = *reinterpret_cast<const int4*>(&g_deg[base + v4 * 4]);
            local[v4 * 4 + 0] = v.x; local[v4 * 4 + 1] = v.y;
            local[v4 * 4 + 2] = v.z; local[v4 * 4 + 3] = v.w;
            sum += v.x + v.y + v.z + v.w;
        }
    } else {
#pragma unroll
        for (int i = 0; i < CH; i++) local[i] = 0;
    }
    if (t < 32) s_w[t] = 0;
    __syncthreads();
    int incl = sum;
#pragma unroll
    for (int off = 1; off < 32; off <<= 1) {
        int v = __shfl_up_sync(0xFFFFFFFFu, incl, off);
        if (lane >= off) incl += v;
    }
    if (lane == 31) s_w[wid] = incl;
    __syncthreads();
    if (wid == 0) {
        int v = s_w[lane];
        int wi = v;
#pragma unroll
        for (int off = 1; off < 32; off <<= 1) {
            int u = __shfl_up_sync(0xFFFFFFFFu, wi, off);
            if (lane >= off) wi += u;
        }
        s_w[lane] = wi - v;
    }
    __syncthreads();
    if (base >= N_NODES) return;
    int excl = s_w[wid] + (incl - sum);
#pragma unroll
    for (int v4 = 0; v4 < 4; v4++) {
        int4 rs; float4 iv;
        int d0 = local[v4 * 4 + 0], d1 = local[v4 * 4 + 1];
        int d2 = local[v4 * 4 + 2], d3 = local[v4 * 4 + 3];
        rs.x = excl;            rs.y = excl + d0;
        rs.z = excl + d0 + d1;  rs.w = excl + d0 + d1 + d2;
        excl += d0 + d1 + d2 + d3;
        iv.x = 1.0f / (float)(d0 > 1 ? d0 : 1);
        iv.y = 1.0f / (float)(d1 > 1 ? d1 : 1);
        iv.z = 1.0f / (float)(d2 > 1 ? d2 : 1);
        iv.w = 1.0f / (float)(d3 > 1 ? d3 : 1);
        *reinterpret_cast<int4*>(&g_rowstart[base + v4 * 4]) = rs;
        *reinterpret_cast<int4*>(&g_cursor[base + v4 * 4])   = rs;
        *reinterpret_cast<float4*>(&g_invdeg[base + v4 * 4]) = iv;
    }
}

__global__ void bucket_kernel(const void* __restrict__ ei) {
    int e = blockIdx.x * blockDim.x + threadIdx.x;
    if (e < N_EDGES) {
        int dst = load_idx(ei, N_EDGES + e);
        int pos = atomicAdd(&g_cursor[dst], 1);
        pos = min(max(pos, 0), N_EDGES - 1);
        g_esrc[pos] = load_idx(ei, e);
    }
}

// ---------------- layer-1 aggregation + A1 pack (single fp16 panel) ----------
__global__ void aggx_pack_kernel(const float* __restrict__ x) {
    int gw = (blockIdx.x * blockDim.x + threadIdx.x) >> 5;
    int lane = threadIdx.x & 31;
    if (gw >= N_NODES) return;
    int beg = g_rowstart[gw];
    int d   = g_cursor[gw] - beg;
    float s0 = 0.f, s1 = 0.f;
    int i = 0;
    for (; i + 4 <= d; i += 4) {
        int sa = g_esrc[beg + i],     sb = g_esrc[beg + i + 1];
        int sc = g_esrc[beg + i + 2], sd = g_esrc[beg + i + 3];
        const float* xa = x + sa * F0;
        const float* xb = x + sb * F0;
        const float* xc = x + sc * F0;
        const float* xd = x + sd * F0;
        s0 += xa[lane] + xb[lane] + xc[lane] + xd[lane];
        if (lane < F0 - 32)
            s1 += xa[lane + 32] + xb[lane + 32] + xc[lane + 32] + xd[lane + 32];
    }
    for (; i < d; i++) {
        const float* xa = x + g_esrc[beg + i] * F0;
        s0 += xa[lane];
        if (lane < F0 - 32) s1 += xa[lane + 32];
    }
    float inv = g_invdeg[gw];
    const float* xs = x + gw * F0;
    __half* o = g_a1h + (size_t)gw * KA1;
    o[lane] = __float2half_rn(s0 * inv);
    if (lane < F0 - 32) o[lane + 32] = __float2half_rn(s1 * inv);
    o[F0 + lane] = __float2half_rn(xs[lane]);
    if (lane < F0 - 32) o[F0 + lane + 32] = __float2half_rn(xs[lane + 32]);
    // cols [100,128) remain zero (never written; zero-init globals)
}

// ---------------- mma.sync GEMM: C[128x128 tile] = A B^T ---------------------
#define BK      64
#define LDPAD   72        // 16-bit elems per smem row (64 + 8 pad) = 144B
#define ROWB    (LDPAD * 2)
#define TILE_B  (128 * ROWB)        // 18432 bytes per operand per stage

template <int MODE>
__global__ void __launch_bounds__(256) mma_gemm_kernel(const float* __restrict__ bias) {
    constexpr int C  = (MODE == 1) ? 2 : 8;
    constexpr int KA = (MODE == 1) ? KA1 : KA2;
    constexpr int KB = (MODE == 1) ? KB1 : KB2;
    const __half* Ag = (MODE == 1) ? g_a1h : g_a2h;
    const __half* Bg = (MODE == 1) ? g_b1h : g_b2p;

    // MODE 2 re-zeroes g_deg for the NEXT kernel_launch call.
    if (MODE == 2) {
        int gid = (blockIdx.y * gridDim.x + blockIdx.x) * blockDim.x + threadIdx.x;
        if (gid < N_NODES) g_deg[gid] = 0;
    }

    extern __shared__ __align__(16) char dsm[];
    uint32_t sb = smem_u32(dsm);

    int tid = threadIdx.x, wid = tid >> 5, lane = tid & 31;
    int wm = wid & 1, wn = wid >> 1;       // warp grid 2 (M) x 4 (N)
    int mbase = blockIdx.y * 128, nbase = blockIdx.x * 128;

    float acc[4][4][4];
#pragma unroll
    for (int i = 0; i < 4; i++)
#pragma unroll
        for (int j = 0; j < 4; j++)
#pragma unroll
            for (int k = 0; k < 4; k++) acc[i][j][k] = 0.f;

    uint32_t a_off[4], b_off[4];
#pragma unroll
    for (int mi = 0; mi < 4; mi++)
        a_off[mi] = (uint32_t)(wm * 64 + mi * 16 + (lane & 15)) * ROWB + (uint32_t)(lane >> 4) * 16u;
#pragma unroll
    for (int ni = 0; ni < 4; ni++)
        b_off[ni] = (uint32_t)(wn * 32 + ni * 8 + (lane & 7)) * ROWB + (uint32_t)((lane >> 3) & 1) * 16u;

    auto load_chunk = [&](int c, int s) {
        uint32_t da = sb + s * 2 * TILE_B;
        uint32_t db = da + TILE_B;
        const __half* asrc = Ag + (size_t)mbase * KA + c * BK;
        const __half* bsrc = Bg + (size_t)nbase * KB + c * BK;
#pragma unroll
        for (int i = 0; i < 4; i++) {
            int seg = tid + i * 256;
            int row = seg >> 3, s16 = seg & 7;
            uint32_t off = row * ROWB + s16 * 16;
            CP16(da + off, asrc + (size_t)row * KA + s16 * 8);
            CP16(db + off, bsrc + (size_t)row * KB + s16 * 8);
        }
        CP_COMMIT();
    };

    load_chunk(0, 0);

    for (int c = 0; c < C; ++c) {
        int s = c & 1;
        if (c + 1 < C) { load_chunk(c + 1, s ^ 1); CP_WAIT(1); }
        else           { CP_WAIT(0); }
        __syncthreads();

        uint32_t As = sb + s * 2 * TILE_B;
        uint32_t Bs = As + TILE_B;
#pragma unroll
        for (int k16 = 0; k16 < BK / 16; ++k16) {
            uint32_t afr[4][4], bfr[4][2];
#pragma unroll
            for (int mi = 0; mi < 4; mi++)
                LDSM_X4(afr[mi][0], afr[mi][1], afr[mi][2], afr[mi][3],
                        As + a_off[mi] + k16 * 32u);
#pragma unroll
            for (int ni = 0; ni < 4; ni++)
                LDSM_X2(bfr[ni][0], bfr[ni][1], Bs + b_off[ni] + k16 * 32u);
#pragma unroll
            for (int mi = 0; mi < 4; mi++)
#pragma unroll
                for (int ni = 0; ni < 4; ni++)
                    mma_fp16(acc[mi][ni], afr[mi], bfr[ni]);
        }
        __syncthreads();
    }

    // ---- epilogue ----
    int lr = lane >> 2, lc = lane & 3;
#pragma unroll
    for (int mi = 0; mi < 4; mi++) {
        int row0 = mbase + wm * 64 + mi * 16 + lr;
        int row1 = row0 + 8;
#pragma unroll
        for (int ni = 0; ni < 4; ni++) {
            int col0 = nbase + wn * 32 + ni * 8 + lc * 2;
            float* d = acc[mi][ni];
            if (MODE == 1) {
                float bb0 = bias[col0], bb1 = bias[col0 + 1];
#pragma unroll
                for (int hf = 0; hf < 2; hf++) {
                    int r = hf ? row1 : row0;
                    if (r >= N_NODES) continue;
                    float v0 = fmaxf(d[hf * 2 + 0] + bb0, 0.f);
                    float v1 = fmaxf(d[hf * 2 + 1] + bb1, 0.f);
                    *reinterpret_cast<__half2*>(&g_a2h[(size_t)r * KA2 + col0]) =
                        __floats2half2_rn(v0, v1);
                }
            } else {
                if (row0 < N_NODES)
                    *reinterpret_cast<float2*>(&g_qr[(size_t)row0 * N2 + col0]) =
                        make_float2(d[0], d[1]);
                if (row1 < N_NODES)
                    *reinterpret_cast<float2*>(&g_qr[(size_t)row1 * N2 + col0]) =
                        make_float2(d[2], d[3]);
            }
        }
    }
}

// ---------------- final: out = mean_agg(q) + r + b2 --------------------------
__global__ void final_kernel(const float* __restrict__ b2, float* __restrict__ out) {
    int gw = (blockIdx.x * blockDim.x + threadIdx.x) >> 5;
    int lane = threadIdx.x & 31;
    if (gw >= N_NODES) return;
    int beg = g_rowstart[gw];
    int d   = g_cursor[gw] - beg;
    int j4 = lane * 4;
    float4 acc = make_float4(0.f, 0.f, 0.f, 0.f);
    int i = 0;
    for (; i + 8 <= d; i += 8) {
        int s0 = g_esrc[beg + i],     s1 = g_esrc[beg + i + 1];
        int s2 = g_esrc[beg + i + 2], s3 = g_esrc[beg + i + 3];
        int s4 = g_esrc[beg + i + 4], s5 = g_esrc[beg + i + 5];
        int s6 = g_esrc[beg + i + 6], s7 = g_esrc[beg + i + 7];
        float4 v0 = *reinterpret_cast<const float4*>(g_qr + (size_t)s0 * N2 + j4);
        float4 v1 = *reinterpret_cast<const float4*>(g_qr + (size_t)s1 * N2 + j4);
        float4 v2 = *reinterpret_cast<const float4*>(g_qr + (size_t)s2 * N2 + j4);
        float4 v3 = *reinterpret_cast<const float4*>(g_qr + (size_t)s3 * N2 + j4);
        float4 v4 = *reinterpret_cast<const float4*>(g_qr + (size_t)s4 * N2 + j4);
        float4 v5 = *reinterpret_cast<const float4*>(g_qr + (size_t)s5 * N2 + j4);
        float4 v6 = *reinterpret_cast<const float4*>(g_qr + (size_t)s6 * N2 + j4);
        float4 v7 = *reinterpret_cast<const float4*>(g_qr + (size_t)s7 * N2 + j4);
        acc.x += (v0.x + v1.x) + (v2.x + v3.x) + (v4.x + v5.x) + (v6.x + v7.x);
        acc.y += (v0.y + v1.y) + (v2.y + v3.y) + (v4.y + v5.y) + (v6.y + v7.y);
        acc.z += (v0.z + v1.z) + (v2.z + v3.z) + (v4.z + v5.z) + (v6.z + v7.z);
        acc.w += (v0.w + v1.w) + (v2.w + v3.w) + (v4.w + v5.w) + (v6.w + v7.w);
    }
    for (; i < d; i++) {
        int s0 = g_esrc[beg + i];
        float4 v0 = *reinterpret_cast<const float4*>(g_qr + (size_t)s0 * N2 + j4);
        acc.x += v0.x; acc.y += v0.y; acc.z += v0.z; acc.w += v0.w;
    }
    float inv = g_invdeg[gw];
    const float* rrow = g_qr + (size_t)gw * N2 + F2;
    float* orow = out + (size_t)gw * F2;
    float av[4] = {acc.x, acc.y, acc.z, acc.w};
#pragma unroll
    for (int c = 0; c < 4; c++) {
        int jj = j4 + c;
        if (jj < F2) orow[jj] = av[c] * inv + rrow[jj] + b2[jj];
    }
}

// ---------------- launch ------------------------------------------------------
extern "C" void kernel_launch(void* const* d_in, const int* in_sizes, int n_in,
                              void* d_out, int out_size) {
    const float* x   = (const float*)d_in[0];
    const void*  ei  = d_in[1];
    const float* W1l = (const float*)d_in[2];
    const float* W1r = (const float*)d_in[3];
    const float* b1  = (const float*)d_in[4];
    const float* W2l = (const float*)d_in[5];
    const float* W2r = (const float*)d_in[6];
    const float* b2  = (const float*)d_in[7];
    float*       out = (float*)d_out;

    const int SMEM_DYN = 4 * TILE_B;   // 73728 bytes: 2 stages x (A + B)
    static bool attr_set = false;
    if (!attr_set) {
        cudaFuncSetAttribute(mma_gemm_kernel<1>, cudaFuncAttributeMaxDynamicSharedMemorySize, SMEM_DYN);
        cudaFuncSetAttribute(mma_gemm_kernel<2>, cudaFuncAttributeMaxDynamicSharedMemorySize, SMEM_DYN);
        attr_set = true;
    }

    const int PREP_ELEMS = HID * 100 + N2 * HID;   // 182272 >= N_EDGES
    prep_kernel<<<(PREP_ELEMS + 255) / 256, 256>>>(ei, W1l, W1r, W2l, W2r);
    scan_kernel<<<1, 640>>>();
    bucket_kernel<<<(N_EDGES + 255) / 256, 256>>>(ei);
    aggx_pack_kernel<<<(N_NODES * 32 + 255) / 256, 256>>>(x);
    mma_gemm_kernel<1><<<dim3(HID / 128, M_PAD / 128), 256, SMEM_DYN>>>(b1);
    mma_gemm_kernel<2><<<dim3(N2 / 128, M_PAD / 128), 256, SMEM_DYN>>>(nullptr);
    final_kernel<<<(N_NODES + 7) / 8, 256>>>(b2, out);
}